// round 9
// baseline (speedup 1.0000x reference)
#include <cuda_runtime.h>
#include <float.h>
#include <math.h>

// Problem constants (fixed by setup_inputs: N=M=16384, dim=3, k=3)
#define N_Q 16384
#define N_R 16384
#define NSEG 32
#define SEGSIZE (N_R / NSEG)    // 512 refs per segment
#define NPAIR   (SEGSIZE / 2)   // 256 packed ref-pairs
#define QBLOCK 128              // threads per CTA
#define QPT 2                   // queries per thread (register blocking)
#define QPERCTA (QBLOCK * QPT)  // 256 queries per CTA
#define K 3
#define NCAND (NSEG * K)        // 96 candidates per query
#define EPS 1e-8f

// Scratch (no cudaMalloc allowed). Layout [seg][cand][query]: coalesced for
// both partial-kernel stores and merge-kernel loads.
// Scores are s = |r|^2/2 - q.r (same ordering as d^2 for a fixed query).
__device__ float g_cand_s[NCAND * N_Q];
__device__ int   g_cand_i[NCAND * N_Q];

// Launch sequence per call = (partial, merge, nop), period 3; harness offset
// o=2 puts ncu "-s 5" on knn_partial_kernel (verified rounds 5/7/8).
__global__ void nop_kernel() {}

__device__ __forceinline__ unsigned long long pk2(float a, float b) {
    unsigned long long r;
    asm("mov.b64 %0, {%1,%2};" : "=l"(r) : "f"(a), "f"(b));
    return r;
}

// Flattened (single-branch-region) top-3 insert on suffix-named state.
#define TOP3_INS(S, s, jj)                                               \
    do {                                                                 \
        const bool lt1 = (s) < b1##S;                                    \
        const bool lt0 = (s) < b0##S;                                    \
        b2##S = lt1 ? b1##S : (s);  i2##S = lt1 ? i1##S : (jj);          \
        const float nb1 = lt0 ? b0##S : (s);                             \
        const int   ni1 = lt0 ? i0##S : (jj);                            \
        b1##S = lt1 ? nb1 : b1##S;  i1##S = lt1 ? ni1 : i1##S;           \
        b0##S = lt0 ? (s) : b0##S;  i0##S = lt0 ? (jj) : i0##S;          \
    } while (0)

// ---------------------------------------------------------------------------
// Kernel 1: each CTA = (256 queries, 2 per thread) x (one 512-ref segment).
// grid = 64 x 32 = 2048 CTAs -> 8192 warps (~55/SM, high occupancy) while
// keeping QPT=2's low LDS-per-pair rate (R8 showed QPT=1 saturates L1).
// Refs staged in smem as packed pairs:
//   sA[p] = (x0,x1 | y0,y1)   sB[p] = (z0,z1 | w0,w1),  w = |r|^2/2
// Inner loop per 2 refs: 2 LDS.128 + 6 fma.rn.f32x2 + 2 FMNMX + 2 FSETP.
// ---------------------------------------------------------------------------
__global__ __launch_bounds__(QBLOCK, 14)
void knn_partial_kernel(const float* __restrict__ qp,
                        const float* __restrict__ rp)
{
    __shared__ ulonglong2 sA[NPAIR];   // 4 KB
    __shared__ ulonglong2 sB[NPAIR];   // 4 KB

    const int qbase = blockIdx.x * QPERCTA;
    const int seg   = blockIdx.y;
    const int rbase = seg * SEGSIZE;
    const int tid   = threadIdx.x;

    // Stage segment refs into packed-pair smem layout (2 iterations).
    for (int p = tid; p < NPAIR; p += QBLOCK) {
        const int r0 = rbase + 2 * p;
        const float x0 = rp[3 * r0 + 0];
        const float y0 = rp[3 * r0 + 1];
        const float z0 = rp[3 * r0 + 2];
        const float x1 = rp[3 * r0 + 3];
        const float y1 = rp[3 * r0 + 4];
        const float z1 = rp[3 * r0 + 5];
        const float w0 = 0.5f * (x0 * x0 + y0 * y0 + z0 * z0);
        const float w1 = 0.5f * (x1 * x1 + y1 * y1 + z1 * z1);
        ulonglong2 A, B;
        A.x = pk2(x0, x1);  A.y = pk2(y0, y1);
        B.x = pk2(z0, z1);  B.y = pk2(w0, w1);
        sA[p] = A;
        sB[p] = B;
    }
    __syncthreads();

    const int qa = qbase + tid;            // query A
    const int qb = qbase + QBLOCK + tid;   // query B
    const unsigned long long ax2 = pk2(-qp[3 * qa + 0], -qp[3 * qa + 0]);
    const unsigned long long ay2 = pk2(-qp[3 * qa + 1], -qp[3 * qa + 1]);
    const unsigned long long az2 = pk2(-qp[3 * qa + 2], -qp[3 * qa + 2]);
    const unsigned long long bx2 = pk2(-qp[3 * qb + 0], -qp[3 * qb + 0]);
    const unsigned long long by2 = pk2(-qp[3 * qb + 1], -qp[3 * qb + 1]);
    const unsigned long long bz2 = pk2(-qp[3 * qb + 2], -qp[3 * qb + 2]);

    float b0a = FLT_MAX, b1a = FLT_MAX, b2a = FLT_MAX;
    int   i0a = 0,       i1a = 0,       i2a = 0;
    float b0b = FLT_MAX, b1b = FLT_MAX, b2b = FLT_MAX;
    int   i0b = 0,       i1b = 0,       i2b = 0;

    #pragma unroll 16
    for (int p = 0; p < NPAIR; ++p) {
        const ulonglong2 A = sA[p];    // broadcast, conflict-free
        const ulonglong2 B = sB[p];
        unsigned long long sa2 = B.y;  // (w0, w1)
        unsigned long long sb2 = B.y;
        asm("fma.rn.f32x2 %0, %1, %2, %0;" : "+l"(sa2) : "l"(ax2), "l"(A.x));
        asm("fma.rn.f32x2 %0, %1, %2, %0;" : "+l"(sa2) : "l"(ay2), "l"(A.y));
        asm("fma.rn.f32x2 %0, %1, %2, %0;" : "+l"(sa2) : "l"(az2), "l"(B.x));
        asm("fma.rn.f32x2 %0, %1, %2, %0;" : "+l"(sb2) : "l"(bx2), "l"(A.x));
        asm("fma.rn.f32x2 %0, %1, %2, %0;" : "+l"(sb2) : "l"(by2), "l"(A.y));
        asm("fma.rn.f32x2 %0, %1, %2, %0;" : "+l"(sb2) : "l"(bz2), "l"(B.x));
        float s0a, s1a, s0b, s1b;
        asm("mov.b64 {%0,%1}, %2;" : "=f"(s0a), "=f"(s1a) : "l"(sa2));
        asm("mov.b64 {%0,%1}, %2;" : "=f"(s0b), "=f"(s1b) : "l"(sb2));

        // One guard per query per 2 refs: pair-min vs current 3rd-best.
        // Index math only inside the (rarer) body.
        if (fminf(s0a, s1a) < b2a) {
            const int j0 = rbase + 2 * p;
            if (s0a < b2a) TOP3_INS(a, s0a, j0);
            if (s1a < b2a) TOP3_INS(a, s1a, j0 + 1);
        }
        if (fminf(s0b, s1b) < b2b) {
            const int j0 = rbase + 2 * p;
            if (s0b < b2b) TOP3_INS(b, s0b, j0);
            if (s1b < b2b) TOP3_INS(b, s1b, j0 + 1);
        }
    }

    // [seg][cand][query] layout: coalesced across contiguous queries.
    const int oa = seg * K * N_Q + qa;
    g_cand_s[oa + 0 * N_Q] = b0a;  g_cand_i[oa + 0 * N_Q] = i0a;
    g_cand_s[oa + 1 * N_Q] = b1a;  g_cand_i[oa + 1 * N_Q] = i1a;
    g_cand_s[oa + 2 * N_Q] = b2a;  g_cand_i[oa + 2 * N_Q] = i2a;
    const int ob = seg * K * N_Q + qb;
    g_cand_s[ob + 0 * N_Q] = b0b;  g_cand_i[ob + 0 * N_Q] = i0b;
    g_cand_s[ob + 1 * N_Q] = b1b;  g_cand_i[ob + 1 * N_Q] = i1b;
    g_cand_s[ob + 2 * N_Q] = b2b;  g_cand_i[ob + 2 * N_Q] = i2b;
}

// ---------------------------------------------------------------------------
// Kernel 2: merge 96 candidates per query -> global top-3, recompute exact
// distances with the reference formula, interpolate flow.
// ---------------------------------------------------------------------------
__global__ __launch_bounds__(64)
void knn_merge_kernel(const float* __restrict__ qp,
                      const float* __restrict__ rp,
                      const float* __restrict__ rf,
                      float* __restrict__ out)
{
    const int q = blockIdx.x * blockDim.x + threadIdx.x;
    if (q >= N_Q) return;

    float b0a = FLT_MAX, b1a = FLT_MAX, b2a = FLT_MAX;
    int   i0a = 0,       i1a = 0,       i2a = 0;

    #pragma unroll 8
    for (int c = 0; c < NCAND; ++c) {
        const float s  = g_cand_s[c * N_Q + q];   // coalesced
        const int   jj = g_cand_i[c * N_Q + q];
        if (s < b2a) TOP3_INS(a, s, jj);
    }

    const float qx = qp[3 * q + 0];
    const float qy = qp[3 * q + 1];
    const float qz = qp[3 * q + 2];
    const float q2 = qx * qx + qy * qy + qz * qz;

    const int idx[K] = { i0a, i1a, i2a };
    float w[K];
    float wsum = 0.0f;
    #pragma unroll
    for (int t = 0; t < K; ++t) {
        const float rx = rp[3 * idx[t] + 0];
        const float ry = rp[3 * idx[t] + 1];
        const float rz = rp[3 * idx[t] + 2];
        const float r2  = rx * rx + ry * ry + rz * rz;
        const float dot = qx * rx + qy * ry + qz * rz;
        const float sq  = q2 + r2 - 2.0f * dot;          // reference formula
        const float d   = sqrtf(fmaxf(sq, 1e-12f));
        w[t] = 1.0f / (d + EPS);
        wsum += w[t];
    }
    const float inv = 1.0f / wsum;

    float ox = 0.0f, oy = 0.0f, oz = 0.0f;
    #pragma unroll
    for (int t = 0; t < K; ++t) {
        const float wt = w[t] * inv;
        ox = fmaf(wt, rf[3 * idx[t] + 0], ox);
        oy = fmaf(wt, rf[3 * idx[t] + 1], oy);
        oz = fmaf(wt, rf[3 * idx[t] + 2], oz);
    }
    out[3 * q + 0] = ox;
    out[3 * q + 1] = oy;
    out[3 * q + 2] = oz;
}

// ---------------------------------------------------------------------------
extern "C" void kernel_launch(void* const* d_in, const int* in_sizes, int n_in,
                              void* d_out, int out_size)
{
    const float* qp = (const float*)d_in[0];   // query_points [16384,3]
    const float* rp = (const float*)d_in[1];   // ref_points   [16384,3]
    const float* rf = (const float*)d_in[2];   // ref_flow     [16384,3]
    float* out = (float*)d_out;                // [16384,3]
    (void)in_sizes; (void)n_in; (void)out_size; // shapes fixed by problem setup

    dim3 grid(N_Q / QPERCTA, NSEG);            // 64 x 32 = 2048 CTAs
    knn_partial_kernel<<<grid, QBLOCK>>>(qp, rp);
    knn_merge_kernel<<<N_Q / 64, 64>>>(qp, rp, rf, out);
    nop_kernel<<<1, 32>>>();                   // period-3 profiler alignment
}

// round 10
// speedup vs baseline: 1.1527x; 1.1527x over previous
#include <cuda_runtime.h>
#include <float.h>
#include <math.h>

// Problem constants (fixed by setup_inputs: N=M=16384, dim=3, k=3)
#define N_Q 16384
#define N_R 16384
#define NSEG 16
#define SEGSIZE (N_R / NSEG)    // 1024 refs per segment
#define NPAIR   (SEGSIZE / 2)   // 512 packed ref-pairs
#define QBLOCK 128              // threads per CTA
#define QPT 2                   // queries per thread (register blocking)
#define QPERCTA (QBLOCK * QPT)  // 256 queries per CTA
#define K 3
#define NCAND (NSEG * K)        // 48 candidates per query
#define EPS 1e-8f

// Scratch (no cudaMalloc allowed). Layout [seg][cand][query]: coalesced for
// both partial-kernel stores and merge-kernel loads.
// Scores are s = |r|^2/2 - q.r (same ordering as d^2 for a fixed query).
__device__ float g_cand_s[NCAND * N_Q];
__device__ int   g_cand_i[NCAND * N_Q];

// Launch sequence per call = (partial, merge, nop), period 3; harness offset
// o=2 puts ncu "-s 5" on knn_partial_kernel (verified rounds 5/7/8/9).
__global__ void nop_kernel() {}

__device__ __forceinline__ unsigned long long pk2(float a, float b) {
    unsigned long long r;
    asm("mov.b64 %0, {%1,%2};" : "=l"(r) : "f"(a), "f"(b));
    return r;
}

// Single-score flattened top-3 insert (guard is at the call site).
// 2 FSETP + 8 SEL, single branch region, no nesting.
#define TOP3_BODY(S, s, jj)                                              \
    do {                                                                 \
        const bool lt1 = (s) < b1##S;                                    \
        const bool lt0 = (s) < b0##S;                                    \
        b2##S = lt1 ? b1##S : (s);  i2##S = lt1 ? i1##S : (jj);          \
        const float nb1 = lt0 ? b0##S : (s);                             \
        const int   ni1 = lt0 ? i0##S : (jj);                            \
        b1##S = lt1 ? nb1 : b1##S;  i1##S = lt1 ? ni1 : i1##S;           \
        b0##S = lt0 ? (s) : b0##S;  i0##S = lt0 ? (jj) : i0##S;          \
    } while (0)

// ---------------------------------------------------------------------------
// Kernel 1: each CTA = (256 queries, 2 per thread) x (one 1024-ref segment).
// grid = 64 x 16 = 1024 CTAs (R7 shape: best measured instr/qr).
// Refs staged in smem as packed pairs:
//   sA[p] = (x0,x1 | y0,y1)   sB[p] = (z0,z1 | w0,w1),  w = |r|^2/2
// Inner loop per 2 refs per query-group: 3 fma.rn.f32x2 + 2 (FSETP+BRA)
// per-score guards; rare 10-op single-score insert bodies.
// ---------------------------------------------------------------------------
__global__ __launch_bounds__(QBLOCK)
void knn_partial_kernel(const float* __restrict__ qp,
                        const float* __restrict__ rp)
{
    __shared__ ulonglong2 sA[NPAIR];   // 8 KB
    __shared__ ulonglong2 sB[NPAIR];   // 8 KB

    const int qbase = blockIdx.x * QPERCTA;
    const int seg   = blockIdx.y;
    const int rbase = seg * SEGSIZE;
    const int tid   = threadIdx.x;

    // Stage segment refs into packed-pair smem layout.
    for (int p = tid; p < NPAIR; p += QBLOCK) {
        const int r0 = rbase + 2 * p;
        const float x0 = rp[3 * r0 + 0];
        const float y0 = rp[3 * r0 + 1];
        const float z0 = rp[3 * r0 + 2];
        const float x1 = rp[3 * r0 + 3];
        const float y1 = rp[3 * r0 + 4];
        const float z1 = rp[3 * r0 + 5];
        const float w0 = 0.5f * (x0 * x0 + y0 * y0 + z0 * z0);
        const float w1 = 0.5f * (x1 * x1 + y1 * y1 + z1 * z1);
        ulonglong2 A, B;
        A.x = pk2(x0, x1);  A.y = pk2(y0, y1);
        B.x = pk2(z0, z1);  B.y = pk2(w0, w1);
        sA[p] = A;
        sB[p] = B;
    }
    __syncthreads();

    const int qa = qbase + tid;            // query A
    const int qb = qbase + QBLOCK + tid;   // query B
    const unsigned long long ax2 = pk2(-qp[3 * qa + 0], -qp[3 * qa + 0]);
    const unsigned long long ay2 = pk2(-qp[3 * qa + 1], -qp[3 * qa + 1]);
    const unsigned long long az2 = pk2(-qp[3 * qa + 2], -qp[3 * qa + 2]);
    const unsigned long long bx2 = pk2(-qp[3 * qb + 0], -qp[3 * qb + 0]);
    const unsigned long long by2 = pk2(-qp[3 * qb + 1], -qp[3 * qb + 1]);
    const unsigned long long bz2 = pk2(-qp[3 * qb + 2], -qp[3 * qb + 2]);

    float b0a = FLT_MAX, b1a = FLT_MAX, b2a = FLT_MAX;
    int   i0a = 0,       i1a = 0,       i2a = 0;
    float b0b = FLT_MAX, b1b = FLT_MAX, b2b = FLT_MAX;
    int   i0b = 0,       i1b = 0,       i2b = 0;

    #pragma unroll 16
    for (int p = 0; p < NPAIR; ++p) {
        const ulonglong2 A = sA[p];    // broadcast, conflict-free
        const ulonglong2 B = sB[p];
        unsigned long long sa2 = B.y;  // (w0, w1)
        unsigned long long sb2 = B.y;
        asm("fma.rn.f32x2 %0, %1, %2, %0;" : "+l"(sa2) : "l"(ax2), "l"(A.x));
        asm("fma.rn.f32x2 %0, %1, %2, %0;" : "+l"(sa2) : "l"(ay2), "l"(A.y));
        asm("fma.rn.f32x2 %0, %1, %2, %0;" : "+l"(sa2) : "l"(az2), "l"(B.x));
        asm("fma.rn.f32x2 %0, %1, %2, %0;" : "+l"(sb2) : "l"(bx2), "l"(A.x));
        asm("fma.rn.f32x2 %0, %1, %2, %0;" : "+l"(sb2) : "l"(by2), "l"(A.y));
        asm("fma.rn.f32x2 %0, %1, %2, %0;" : "+l"(sb2) : "l"(bz2), "l"(B.x));
        float s0a, s1a, s0b, s1b;
        asm("mov.b64 {%0,%1}, %2;" : "=f"(s0a), "=f"(s1a) : "l"(sa2));
        asm("mov.b64 {%0,%1}, %2;" : "=f"(s0b), "=f"(s1b) : "l"(sb2));

        // Per-score guards: 1 FSETP + 1 predicated branch each; the 10-op
        // insert body runs only on the rare taken path. Index math folded
        // into the body (p is an unroll constant).
        if (s0a < b2a) TOP3_BODY(a, s0a, rbase + 2 * p);
        if (s1a < b2a) TOP3_BODY(a, s1a, rbase + 2 * p + 1);
        if (s0b < b2b) TOP3_BODY(b, s0b, rbase + 2 * p);
        if (s1b < b2b) TOP3_BODY(b, s1b, rbase + 2 * p + 1);
    }

    // [seg][cand][query] layout: coalesced across contiguous queries.
    const int oa = seg * K * N_Q + qa;
    g_cand_s[oa + 0 * N_Q] = b0a;  g_cand_i[oa + 0 * N_Q] = i0a;
    g_cand_s[oa + 1 * N_Q] = b1a;  g_cand_i[oa + 1 * N_Q] = i1a;
    g_cand_s[oa + 2 * N_Q] = b2a;  g_cand_i[oa + 2 * N_Q] = i2a;
    const int ob = seg * K * N_Q + qb;
    g_cand_s[ob + 0 * N_Q] = b0b;  g_cand_i[ob + 0 * N_Q] = i0b;
    g_cand_s[ob + 1 * N_Q] = b1b;  g_cand_i[ob + 1 * N_Q] = i1b;
    g_cand_s[ob + 2 * N_Q] = b2b;  g_cand_i[ob + 2 * N_Q] = i2b;
}

// ---------------------------------------------------------------------------
// Kernel 2: merge 48 candidates per query -> global top-3, recompute exact
// distances with the reference formula, interpolate flow.
// ---------------------------------------------------------------------------
__global__ __launch_bounds__(64)
void knn_merge_kernel(const float* __restrict__ qp,
                      const float* __restrict__ rp,
                      const float* __restrict__ rf,
                      float* __restrict__ out)
{
    const int q = blockIdx.x * blockDim.x + threadIdx.x;
    if (q >= N_Q) return;

    float b0a = FLT_MAX, b1a = FLT_MAX, b2a = FLT_MAX;
    int   i0a = 0,       i1a = 0,       i2a = 0;

    #pragma unroll 8
    for (int c = 0; c < NCAND; ++c) {
        const float s  = g_cand_s[c * N_Q + q];   // coalesced
        const int   jj = g_cand_i[c * N_Q + q];
        if (s < b2a) TOP3_BODY(a, s, jj);
    }

    const float qx = qp[3 * q + 0];
    const float qy = qp[3 * q + 1];
    const float qz = qp[3 * q + 2];
    const float q2 = qx * qx + qy * qy + qz * qz;

    const int idx[K] = { i0a, i1a, i2a };
    float w[K];
    float wsum = 0.0f;
    #pragma unroll
    for (int t = 0; t < K; ++t) {
        const float rx = rp[3 * idx[t] + 0];
        const float ry = rp[3 * idx[t] + 1];
        const float rz = rp[3 * idx[t] + 2];
        const float r2  = rx * rx + ry * ry + rz * rz;
        const float dot = qx * rx + qy * ry + qz * rz;
        const float sq  = q2 + r2 - 2.0f * dot;          // reference formula
        const float d   = sqrtf(fmaxf(sq, 1e-12f));
        w[t] = 1.0f / (d + EPS);
        wsum += w[t];
    }
    const float inv = 1.0f / wsum;

    float ox = 0.0f, oy = 0.0f, oz = 0.0f;
    #pragma unroll
    for (int t = 0; t < K; ++t) {
        const float wt = w[t] * inv;
        ox = fmaf(wt, rf[3 * idx[t] + 0], ox);
        oy = fmaf(wt, rf[3 * idx[t] + 1], oy);
        oz = fmaf(wt, rf[3 * idx[t] + 2], oz);
    }
    out[3 * q + 0] = ox;
    out[3 * q + 1] = oy;
    out[3 * q + 2] = oz;
}

// ---------------------------------------------------------------------------
extern "C" void kernel_launch(void* const* d_in, const int* in_sizes, int n_in,
                              void* d_out, int out_size)
{
    const float* qp = (const float*)d_in[0];   // query_points [16384,3]
    const float* rp = (const float*)d_in[1];   // ref_points   [16384,3]
    const float* rf = (const float*)d_in[2];   // ref_flow     [16384,3]
    float* out = (float*)d_out;                // [16384,3]
    (void)in_sizes; (void)n_in; (void)out_size; // shapes fixed by problem setup

    dim3 grid(N_Q / QPERCTA, NSEG);            // 64 x 16 = 1024 CTAs
    knn_partial_kernel<<<grid, QBLOCK>>>(qp, rp);
    knn_merge_kernel<<<N_Q / 64, 64>>>(qp, rp, rf, out);
    nop_kernel<<<1, 32>>>();                   // period-3 profiler alignment
}

// round 12
// speedup vs baseline: 2.2986x; 1.9941x over previous
#include <cuda_runtime.h>
#include <float.h>
#include <math.h>

// Problem constants (fixed by setup_inputs: N=M=16384, dim=3, k=3)
#define N_Q 16384
#define N_R 16384
#define NSEG 128                 // rescan granularity: 128 segments of 128 refs
#define SEGSIZE (N_R / NSEG)     // 128
#define SEGS_PER_CTA 4
#define REFS_PER_CTA (SEGSIZE * SEGS_PER_CTA)   // 512
#define PAIRS_PER_CTA (REFS_PER_CTA / 2)        // 256
#define PAIRS_PER_SEG (SEGSIZE / 2)             // 64
#define QBLOCK 128               // threads per CTA
#define QPT 2                    // queries per thread
#define QPERCTA (QBLOCK * QPT)   // 256
#define K 3
#define EPS 1e-8f

// Per-(query, segment) MIN score, [query][seg] layout (8 MB scratch).
// Score s = |r|^2/2 - q.r : same per-query ordering as distance.
__device__ float g_min[N_Q * NSEG];

// Launch sequence per call = (phaseA, phaseB, nop), period 3; harness offset
// o=2 puts ncu "-s 5" on knn_segmin_kernel.
__global__ void nop_kernel() {}

typedef unsigned long long u64;

__device__ __forceinline__ u64 pk2(float a, float b) {
    u64 r;
    asm("mov.b64 %0, {%1,%2};" : "=l"(r) : "f"(a), "f"(b));
    return r;
}
__device__ __forceinline__ void upk2(float& a, float& b, u64 v) {
    asm("mov.b64 {%0,%1}, %2;" : "=f"(a), "=f"(b) : "l"(v));
}
#define FMA2(acc, a, b) asm("fma.rn.f32x2 %0, %1, %2, %0;" : "+l"(acc) : "l"(a), "l"(b))

// Guarded scalar top-3 insert WITH index (only in the tiny rescan phase).
#define TOP3_IDX(s, r)                                                   \
    do {                                                                 \
        if ((s) < b2) {                                                  \
            const bool lt1 = (s) < b1;                                   \
            const bool lt0 = (s) < b0;                                   \
            b2 = lt1 ? b1 : (s);   i2 = lt1 ? i1 : (r);                  \
            const float nb1 = lt0 ? b0 : (s);                            \
            const int   ni1 = lt0 ? i0 : (r);                            \
            b1 = lt1 ? nb1 : b1;   i1 = lt1 ? ni1 : i1;                  \
            b0 = lt0 ? (s) : b0;   i0 = lt0 ? (r) : i0;                  \
        }                                                                \
    } while (0)

// ---------------------------------------------------------------------------
// Phase A: branchless per-segment MIN.
// CTA = (256 queries, 2/thread) x (4 segments = 512 refs staged in smem).
// grid = 64 x 32 = 2048 CTAs -> 8192 warps.
// Inner iter (2 refs x 2 queries): 2 LDS.128 + 6 fma.f32x2 + 4 FMNMX. No branches.
// ---------------------------------------------------------------------------
__global__ __launch_bounds__(QBLOCK)
void knn_segmin_kernel(const float* __restrict__ qp,
                       const float* __restrict__ rp)
{
    __shared__ ulonglong2 sA[PAIRS_PER_CTA];   // 4 KB  (x0,x1 | y0,y1)
    __shared__ ulonglong2 sB[PAIRS_PER_CTA];   // 4 KB  (z0,z1 | w0,w1)

    const int qbase   = blockIdx.x * QPERCTA;
    const int segbase = blockIdx.y * SEGS_PER_CTA;
    const int rbase   = segbase * SEGSIZE;
    const int tid     = threadIdx.x;

    for (int p = tid; p < PAIRS_PER_CTA; p += QBLOCK) {
        const int r0 = rbase + 2 * p;
        const float x0 = rp[3 * r0 + 0];
        const float y0 = rp[3 * r0 + 1];
        const float z0 = rp[3 * r0 + 2];
        const float x1 = rp[3 * r0 + 3];
        const float y1 = rp[3 * r0 + 4];
        const float z1 = rp[3 * r0 + 5];
        // w = |r|^2/2 — EXACT same fma chain as phase-B rescan.
        const float w0 = 0.5f * fmaf(z0, z0, fmaf(y0, y0, x0 * x0));
        const float w1 = 0.5f * fmaf(z1, z1, fmaf(y1, y1, x1 * x1));
        ulonglong2 A, B;
        A.x = pk2(x0, x1);  A.y = pk2(y0, y1);
        B.x = pk2(z0, z1);  B.y = pk2(w0, w1);
        sA[p] = A;
        sB[p] = B;
    }
    __syncthreads();

    const int qa = qbase + tid;
    const int qb = qbase + QBLOCK + tid;
    const u64 ax2 = pk2(-qp[3 * qa + 0], -qp[3 * qa + 0]);
    const u64 ay2 = pk2(-qp[3 * qa + 1], -qp[3 * qa + 1]);
    const u64 az2 = pk2(-qp[3 * qa + 2], -qp[3 * qa + 2]);
    const u64 bx2 = pk2(-qp[3 * qb + 0], -qp[3 * qb + 0]);
    const u64 by2 = pk2(-qp[3 * qb + 1], -qp[3 * qb + 1]);
    const u64 bz2 = pk2(-qp[3 * qb + 2], -qp[3 * qb + 2]);

    float4 outA, outB;
    float* oa = (float*)&outA;
    float* ob = (float*)&outB;

    #pragma unroll
    for (int sb = 0; sb < SEGS_PER_CTA; ++sb) {
        float mEa = FLT_MAX, mOa = FLT_MAX, mEb = FLT_MAX, mOb = FLT_MAX;
        const int p0 = sb * PAIRS_PER_SEG;
        #pragma unroll 8
        for (int p = p0; p < p0 + PAIRS_PER_SEG; ++p) {
            const ulonglong2 A = sA[p];    // broadcast, conflict-free
            const ulonglong2 B = sB[p];
            u64 sa2 = B.y;                 // (w0, w1)
            u64 sb2 = B.y;
            FMA2(sa2, ax2, A.x);  FMA2(sa2, ay2, A.y);  FMA2(sa2, az2, B.x);
            FMA2(sb2, bx2, A.x);  FMA2(sb2, by2, A.y);  FMA2(sb2, bz2, B.x);
            float s0a, s1a, s0b, s1b;
            upk2(s0a, s1a, sa2);
            upk2(s0b, s1b, sb2);
            mEa = fminf(mEa, s0a);  mOa = fminf(mOa, s1a);
            mEb = fminf(mEb, s0b);  mOb = fminf(mOb, s1b);
        }
        oa[sb] = fminf(mEa, mOa);
        ob[sb] = fminf(mEb, mOb);
    }

    // [query][seg] layout; 16B-aligned float4 stores (segbase multiple of 4).
    *reinterpret_cast<float4*>(&g_min[qa * NSEG + segbase]) = outA;
    *reinterpret_cast<float4*>(&g_min[qb * NSEG + segbase]) = outB;
}

// ---------------------------------------------------------------------------
// Phase B: one WARP per query.
// (a) load 128 segment-mins (coalesced), warp-reduce to 3rd-smallest t
// (b) ballot-flag segments with min <= t(+margin)  -> ~3 segments
// (c) rescan flagged segments (128 refs each, 4/lane) with index tracking
// (d) lane 0: exact reference-formula distances + flow interpolation
// ---------------------------------------------------------------------------
__global__ __launch_bounds__(128)
void knn_finish_kernel(const float* __restrict__ qp,
                       const float* __restrict__ rp,
                       const float* __restrict__ rf,
                       float* __restrict__ out)
{
    const int q    = (blockIdx.x * 128 + threadIdx.x) >> 5;
    const int lane = threadIdx.x & 31;

    // (a) per-lane sorted triple over its 4 segment-mins
    float m4[4];
    float v0 = FLT_MAX, v1 = FLT_MAX, v2 = FLT_MAX;
    #pragma unroll
    for (int t = 0; t < 4; ++t) {
        const float s = g_min[q * NSEG + 32 * t + lane];   // coalesced
        m4[t] = s;
        const float m0 = fminf(s, v0);
        const float u0 = fmaxf(s, v0);
        const float m1 = fminf(u0, v1);
        const float u1 = fmaxf(u0, v1);
        v0 = m0;  v1 = m1;  v2 = fminf(u1, v2);
    }
    // warp merge of sorted triples
    #pragma unroll
    for (int off = 16; off; off >>= 1) {
        const float p0 = __shfl_down_sync(0xffffffffu, v0, off);
        const float p1 = __shfl_down_sync(0xffffffffu, v1, off);
        const float p2 = __shfl_down_sync(0xffffffffu, v2, off);
        const float c0 = fminf(v0, p0);
        const float u  = fmaxf(v0, p0);
        const float vv = fminf(v1, p1);
        const float w  = fmaxf(v1, p1);
        const float c1 = fminf(u, vv);
        const float x  = fmaxf(u, vv);
        const float c2 = fminf(fminf(x, w), fminf(v2, p2));
        v0 = c0;  v1 = c1;  v2 = c2;
    }
    float t3 = __shfl_sync(0xffffffffu, v2, 0);
    // margin: covers cross-kernel fma-rounding skew (scores |s| ~ 1e3)
    t3 += fmaxf(fabsf(t3) * 1e-5f, 1e-5f);

    // (b) flag segments: word t, bit lane <-> segment 32*t+lane
    unsigned ball[4];
    #pragma unroll
    for (int t = 0; t < 4; ++t)
        ball[t] = __ballot_sync(0xffffffffu, m4[t] <= t3);

    const float qx = qp[3 * q + 0];
    const float qy = qp[3 * q + 1];
    const float qz = qp[3 * q + 2];
    const float nqx = -qx, nqy = -qy, nqz = -qz;

    // (c) rescan flagged segments, 4 refs per lane per segment
    float b0 = FLT_MAX, b1 = FLT_MAX, b2 = FLT_MAX;
    int   i0 = 0,       i1 = 0,       i2 = 0;
    #pragma unroll
    for (int wdi = 0; wdi < 4; ++wdi) {
        unsigned m = ball[wdi];
        while (m) {
            const int seg = 32 * wdi + (__ffs(m) - 1);
            m &= m - 1;
            const int base = seg * SEGSIZE;
            #pragma unroll
            for (int t = 0; t < SEGSIZE / 32; ++t) {
                const int r = base + 32 * t + lane;        // coalesced
                const float rx = rp[3 * r + 0];
                const float ry = rp[3 * r + 1];
                const float rz = rp[3 * r + 2];
                const float wr = 0.5f * fmaf(rz, rz, fmaf(ry, ry, rx * rx));
                const float s  = fmaf(nqz, rz, fmaf(nqy, ry, fmaf(nqx, rx, wr)));
                TOP3_IDX(s, r);
            }
        }
    }
    // cross-lane reduce (score,index) triples
    #pragma unroll
    for (int off = 16; off; off >>= 1) {
        const float pb0 = __shfl_down_sync(0xffffffffu, b0, off);
        const float pb1 = __shfl_down_sync(0xffffffffu, b1, off);
        const float pb2 = __shfl_down_sync(0xffffffffu, b2, off);
        const int   pi0 = __shfl_down_sync(0xffffffffu, i0, off);
        const int   pi1 = __shfl_down_sync(0xffffffffu, i1, off);
        const int   pi2 = __shfl_down_sync(0xffffffffu, i2, off);
        TOP3_IDX(pb0, pi0);
        TOP3_IDX(pb1, pi1);
        TOP3_IDX(pb2, pi2);
    }

    // (d) lane 0: exact recompute per reference formula + interpolation
    if (lane == 0) {
        const float q2 = qx * qx + qy * qy + qz * qz;
        const int idx[K] = { i0, i1, i2 };
        float w[K];
        float wsum = 0.0f;
        #pragma unroll
        for (int t = 0; t < K; ++t) {
            const float rx = rp[3 * idx[t] + 0];
            const float ry = rp[3 * idx[t] + 1];
            const float rz = rp[3 * idx[t] + 2];
            const float r2  = rx * rx + ry * ry + rz * rz;
            const float dot = qx * rx + qy * ry + qz * rz;
            const float sq  = q2 + r2 - 2.0f * dot;       // reference formula
            const float d   = sqrtf(fmaxf(sq, 1e-12f));
            w[t] = 1.0f / (d + EPS);
            wsum += w[t];
        }
        const float inv = 1.0f / wsum;
        float ox = 0.0f, oy = 0.0f, oz = 0.0f;
        #pragma unroll
        for (int t = 0; t < K; ++t) {
            const float wt = w[t] * inv;
            ox = fmaf(wt, rf[3 * idx[t] + 0], ox);
            oy = fmaf(wt, rf[3 * idx[t] + 1], oy);
            oz = fmaf(wt, rf[3 * idx[t] + 2], oz);
        }
        out[3 * q + 0] = ox;
        out[3 * q + 1] = oy;
        out[3 * q + 2] = oz;
    }
}

// ---------------------------------------------------------------------------
extern "C" void kernel_launch(void* const* d_in, const int* in_sizes, int n_in,
                              void* d_out, int out_size)
{
    const float* qp = (const float*)d_in[0];   // query_points [16384,3]
    const float* rp = (const float*)d_in[1];   // ref_points   [16384,3]
    const float* rf = (const float*)d_in[2];   // ref_flow     [16384,3]
    float* out = (float*)d_out;                // [16384,3]
    (void)in_sizes; (void)n_in; (void)out_size;

    dim3 gridA(N_Q / QPERCTA, NSEG / SEGS_PER_CTA);   // 64 x 32 = 2048 CTAs
    knn_segmin_kernel<<<gridA, QBLOCK>>>(qp, rp);
    knn_finish_kernel<<<N_Q / 4, 128>>>(qp, rp, rf, out);  // warp per query
    nop_kernel<<<1, 32>>>();                   // period-3 profiler alignment
}

// round 13
// speedup vs baseline: 2.3813x; 1.0360x over previous
#include <cuda_runtime.h>
#include <float.h>
#include <math.h>

// Problem constants (fixed by setup_inputs: N=M=16384, dim=3, k=3)
#define N_Q 16384
#define N_R 16384
#define NSEG 128                 // rescan granularity: 128 segments of 128 refs
#define SEGSIZE (N_R / NSEG)     // 128
#define SEGS_PER_CTA 4
#define REFS_PER_CTA (SEGSIZE * SEGS_PER_CTA)   // 512
#define PAIRS_PER_CTA (REFS_PER_CTA / 2)        // 256
#define PAIRS_PER_SEG (SEGSIZE / 2)             // 64
#define QBLOCK 128               // threads per CTA
#define QPT 4                    // queries per thread (amortize LDS 2x vs R12)
#define QPERCTA (QBLOCK * QPT)   // 512
#define K 3
#define EPS 1e-8f

// Per-(query, segment) MIN score, [query][seg] layout (8 MB scratch).
// Score s = |r|^2/2 - q.r : same per-query ordering as distance.
__device__ float g_min[N_Q * NSEG];

// Launch sequence per call = (phaseA, phaseB, nop), period 3; harness offset
// o=2 puts ncu "-s 5" on knn_segmin_kernel.
__global__ void nop_kernel() {}

typedef unsigned long long u64;

__device__ __forceinline__ u64 pk2(float a, float b) {
    u64 r;
    asm("mov.b64 %0, {%1,%2};" : "=l"(r) : "f"(a), "f"(b));
    return r;
}
__device__ __forceinline__ void upk2(float& a, float& b, u64 v) {
    asm("mov.b64 {%0,%1}, %2;" : "=f"(a), "=f"(b) : "l"(v));
}
#define FMA2(acc, a, b) asm("fma.rn.f32x2 %0, %1, %2, %0;" : "+l"(acc) : "l"(a), "l"(b))

// Guarded scalar top-3 insert WITH index (only in the tiny rescan phase).
#define TOP3_IDX(s, r)                                                   \
    do {                                                                 \
        if ((s) < b2) {                                                  \
            const bool lt1 = (s) < b1;                                   \
            const bool lt0 = (s) < b0;                                   \
            b2 = lt1 ? b1 : (s);   i2 = lt1 ? i1 : (r);                  \
            const float nb1 = lt0 ? b0 : (s);                            \
            const int   ni1 = lt0 ? i0 : (r);                            \
            b1 = lt1 ? nb1 : b1;   i1 = lt1 ? ni1 : i1;                  \
            b0 = lt0 ? (s) : b0;   i0 = lt0 ? (r) : i0;                  \
        }                                                                \
    } while (0)

// ---------------------------------------------------------------------------
// Phase A: branchless per-segment MIN.
// CTA = (512 queries, 4/thread) x (4 segments = 512 refs staged in smem).
// grid = 32 x 32 = 1024 CTAs -> 4096 warps.
// Inner iter (2 refs x 4 queries): 2 LDS.128 + 12 fma.f32x2 + 8 FMNMX.
// 12 independent fma chains + 8 independent min chains -> high ILP.
// ---------------------------------------------------------------------------
__global__ __launch_bounds__(QBLOCK)
void knn_segmin_kernel(const float* __restrict__ qp,
                       const float* __restrict__ rp)
{
    __shared__ ulonglong2 sA[PAIRS_PER_CTA];   // 4 KB  (x0,x1 | y0,y1)
    __shared__ ulonglong2 sB[PAIRS_PER_CTA];   // 4 KB  (z0,z1 | w0,w1)

    const int qbase   = blockIdx.x * QPERCTA;
    const int segbase = blockIdx.y * SEGS_PER_CTA;
    const int rbase   = segbase * SEGSIZE;
    const int tid     = threadIdx.x;

    for (int p = tid; p < PAIRS_PER_CTA; p += QBLOCK) {
        const int r0 = rbase + 2 * p;
        const float x0 = rp[3 * r0 + 0];
        const float y0 = rp[3 * r0 + 1];
        const float z0 = rp[3 * r0 + 2];
        const float x1 = rp[3 * r0 + 3];
        const float y1 = rp[3 * r0 + 4];
        const float z1 = rp[3 * r0 + 5];
        // w = |r|^2/2 — EXACT same fma chain as phase-B rescan.
        const float w0 = 0.5f * fmaf(z0, z0, fmaf(y0, y0, x0 * x0));
        const float w1 = 0.5f * fmaf(z1, z1, fmaf(y1, y1, x1 * x1));
        ulonglong2 A, B;
        A.x = pk2(x0, x1);  A.y = pk2(y0, y1);
        B.x = pk2(z0, z1);  B.y = pk2(w0, w1);
        sA[p] = A;
        sB[p] = B;
    }
    __syncthreads();

    const int qa = qbase + tid;
    const int qb = qa + QBLOCK;
    const int qc = qb + QBLOCK;
    const int qd = qc + QBLOCK;
    const u64 ax2 = pk2(-qp[3 * qa + 0], -qp[3 * qa + 0]);
    const u64 ay2 = pk2(-qp[3 * qa + 1], -qp[3 * qa + 1]);
    const u64 az2 = pk2(-qp[3 * qa + 2], -qp[3 * qa + 2]);
    const u64 bx2 = pk2(-qp[3 * qb + 0], -qp[3 * qb + 0]);
    const u64 by2 = pk2(-qp[3 * qb + 1], -qp[3 * qb + 1]);
    const u64 bz2 = pk2(-qp[3 * qb + 2], -qp[3 * qb + 2]);
    const u64 cx2 = pk2(-qp[3 * qc + 0], -qp[3 * qc + 0]);
    const u64 cy2 = pk2(-qp[3 * qc + 1], -qp[3 * qc + 1]);
    const u64 cz2 = pk2(-qp[3 * qc + 2], -qp[3 * qc + 2]);
    const u64 dx2 = pk2(-qp[3 * qd + 0], -qp[3 * qd + 0]);
    const u64 dy2 = pk2(-qp[3 * qd + 1], -qp[3 * qd + 1]);
    const u64 dz2 = pk2(-qp[3 * qd + 2], -qp[3 * qd + 2]);

    float4 outA, outB, outC, outD;
    float* oa = (float*)&outA;
    float* ob = (float*)&outB;
    float* oc = (float*)&outC;
    float* od = (float*)&outD;

    #pragma unroll
    for (int sb = 0; sb < SEGS_PER_CTA; ++sb) {
        float mEa = FLT_MAX, mOa = FLT_MAX, mEb = FLT_MAX, mOb = FLT_MAX;
        float mEc = FLT_MAX, mOc = FLT_MAX, mEd = FLT_MAX, mOd = FLT_MAX;
        const int p0 = sb * PAIRS_PER_SEG;
        #pragma unroll 8
        for (int p = p0; p < p0 + PAIRS_PER_SEG; ++p) {
            const ulonglong2 A = sA[p];    // broadcast, conflict-free
            const ulonglong2 B = sB[p];
            u64 sa2 = B.y;                 // (w0, w1)
            u64 sb2 = B.y;
            u64 sc2 = B.y;
            u64 sd2 = B.y;
            FMA2(sa2, ax2, A.x);  FMA2(sa2, ay2, A.y);  FMA2(sa2, az2, B.x);
            FMA2(sb2, bx2, A.x);  FMA2(sb2, by2, A.y);  FMA2(sb2, bz2, B.x);
            FMA2(sc2, cx2, A.x);  FMA2(sc2, cy2, A.y);  FMA2(sc2, cz2, B.x);
            FMA2(sd2, dx2, A.x);  FMA2(sd2, dy2, A.y);  FMA2(sd2, dz2, B.x);
            float s0, s1;
            upk2(s0, s1, sa2);  mEa = fminf(mEa, s0);  mOa = fminf(mOa, s1);
            upk2(s0, s1, sb2);  mEb = fminf(mEb, s0);  mOb = fminf(mOb, s1);
            upk2(s0, s1, sc2);  mEc = fminf(mEc, s0);  mOc = fminf(mOc, s1);
            upk2(s0, s1, sd2);  mEd = fminf(mEd, s0);  mOd = fminf(mOd, s1);
        }
        oa[sb] = fminf(mEa, mOa);
        ob[sb] = fminf(mEb, mOb);
        oc[sb] = fminf(mEc, mOc);
        od[sb] = fminf(mEd, mOd);
    }

    // [query][seg] layout; 16B-aligned float4 stores (segbase multiple of 4).
    *reinterpret_cast<float4*>(&g_min[qa * NSEG + segbase]) = outA;
    *reinterpret_cast<float4*>(&g_min[qb * NSEG + segbase]) = outB;
    *reinterpret_cast<float4*>(&g_min[qc * NSEG + segbase]) = outC;
    *reinterpret_cast<float4*>(&g_min[qd * NSEG + segbase]) = outD;
}

// ---------------------------------------------------------------------------
// Phase B: one WARP per query.
// (a) load 128 segment-mins (coalesced), warp-reduce to 3rd-smallest t
// (b) ballot-flag segments with min <= t(+margin)  -> ~3 segments
// (c) rescan flagged segments (128 refs each, 4/lane) with index tracking
// (d) lane 0: exact reference-formula distances + flow interpolation
// ---------------------------------------------------------------------------
__global__ __launch_bounds__(128)
void knn_finish_kernel(const float* __restrict__ qp,
                       const float* __restrict__ rp,
                       const float* __restrict__ rf,
                       float* __restrict__ out)
{
    const int q    = (blockIdx.x * 128 + threadIdx.x) >> 5;
    const int lane = threadIdx.x & 31;

    // (a) per-lane sorted triple over its 4 segment-mins
    float m4[4];
    float v0 = FLT_MAX, v1 = FLT_MAX, v2 = FLT_MAX;
    #pragma unroll
    for (int t = 0; t < 4; ++t) {
        const float s = g_min[q * NSEG + 32 * t + lane];   // coalesced
        m4[t] = s;
        const float m0 = fminf(s, v0);
        const float u0 = fmaxf(s, v0);
        const float m1 = fminf(u0, v1);
        const float u1 = fmaxf(u0, v1);
        v0 = m0;  v1 = m1;  v2 = fminf(u1, v2);
    }
    // warp merge of sorted triples
    #pragma unroll
    for (int off = 16; off; off >>= 1) {
        const float p0 = __shfl_down_sync(0xffffffffu, v0, off);
        const float p1 = __shfl_down_sync(0xffffffffu, v1, off);
        const float p2 = __shfl_down_sync(0xffffffffu, v2, off);
        const float c0 = fminf(v0, p0);
        const float u  = fmaxf(v0, p0);
        const float vv = fminf(v1, p1);
        const float w  = fmaxf(v1, p1);
        const float c1 = fminf(u, vv);
        const float x  = fmaxf(u, vv);
        const float c2 = fminf(fminf(x, w), fminf(v2, p2));
        v0 = c0;  v1 = c1;  v2 = c2;
    }
    float t3 = __shfl_sync(0xffffffffu, v2, 0);
    // margin: covers cross-kernel fma-rounding skew (scores |s| ~ 1e3)
    t3 += fmaxf(fabsf(t3) * 1e-5f, 1e-5f);

    // (b) flag segments: word t, bit lane <-> segment 32*t+lane
    unsigned ball[4];
    #pragma unroll
    for (int t = 0; t < 4; ++t)
        ball[t] = __ballot_sync(0xffffffffu, m4[t] <= t3);

    const float qx = qp[3 * q + 0];
    const float qy = qp[3 * q + 1];
    const float qz = qp[3 * q + 2];
    const float nqx = -qx, nqy = -qy, nqz = -qz;

    // (c) rescan flagged segments, 4 refs per lane per segment
    float b0 = FLT_MAX, b1 = FLT_MAX, b2 = FLT_MAX;
    int   i0 = 0,       i1 = 0,       i2 = 0;
    #pragma unroll
    for (int wdi = 0; wdi < 4; ++wdi) {
        unsigned m = ball[wdi];
        while (m) {
            const int seg = 32 * wdi + (__ffs(m) - 1);
            m &= m - 1;
            const int base = seg * SEGSIZE;
            #pragma unroll
            for (int t = 0; t < SEGSIZE / 32; ++t) {
                const int r = base + 32 * t + lane;        // coalesced
                const float rx = rp[3 * r + 0];
                const float ry = rp[3 * r + 1];
                const float rz = rp[3 * r + 2];
                const float wr = 0.5f * fmaf(rz, rz, fmaf(ry, ry, rx * rx));
                const float s  = fmaf(nqz, rz, fmaf(nqy, ry, fmaf(nqx, rx, wr)));
                TOP3_IDX(s, r);
            }
        }
    }
    // cross-lane reduce (score,index) triples
    #pragma unroll
    for (int off = 16; off; off >>= 1) {
        const float pb0 = __shfl_down_sync(0xffffffffu, b0, off);
        const float pb1 = __shfl_down_sync(0xffffffffu, b1, off);
        const float pb2 = __shfl_down_sync(0xffffffffu, b2, off);
        const int   pi0 = __shfl_down_sync(0xffffffffu, i0, off);
        const int   pi1 = __shfl_down_sync(0xffffffffu, i1, off);
        const int   pi2 = __shfl_down_sync(0xffffffffu, i2, off);
        TOP3_IDX(pb0, pi0);
        TOP3_IDX(pb1, pi1);
        TOP3_IDX(pb2, pi2);
    }

    // (d) lane 0: exact recompute per reference formula + interpolation
    if (lane == 0) {
        const float q2 = qx * qx + qy * qy + qz * qz;
        const int idx[K] = { i0, i1, i2 };
        float w[K];
        float wsum = 0.0f;
        #pragma unroll
        for (int t = 0; t < K; ++t) {
            const float rx = rp[3 * idx[t] + 0];
            const float ry = rp[3 * idx[t] + 1];
            const float rz = rp[3 * idx[t] + 2];
            const float r2  = rx * rx + ry * ry + rz * rz;
            const float dot = qx * rx + qy * ry + qz * rz;
            const float sq  = q2 + r2 - 2.0f * dot;       // reference formula
            const float d   = sqrtf(fmaxf(sq, 1e-12f));
            w[t] = 1.0f / (d + EPS);
            wsum += w[t];
        }
        const float inv = 1.0f / wsum;
        float ox = 0.0f, oy = 0.0f, oz = 0.0f;
        #pragma unroll
        for (int t = 0; t < K; ++t) {
            const float wt = w[t] * inv;
            ox = fmaf(wt, rf[3 * idx[t] + 0], ox);
            oy = fmaf(wt, rf[3 * idx[t] + 1], oy);
            oz = fmaf(wt, rf[3 * idx[t] + 2], oz);
        }
        out[3 * q + 0] = ox;
        out[3 * q + 1] = oy;
        out[3 * q + 2] = oz;
    }
}

// ---------------------------------------------------------------------------
extern "C" void kernel_launch(void* const* d_in, const int* in_sizes, int n_in,
                              void* d_out, int out_size)
{
    const float* qp = (const float*)d_in[0];   // query_points [16384,3]
    const float* rp = (const float*)d_in[1];   // ref_points   [16384,3]
    const float* rf = (const float*)d_in[2];   // ref_flow     [16384,3]
    float* out = (float*)d_out;                // [16384,3]
    (void)in_sizes; (void)n_in; (void)out_size;

    dim3 gridA(N_Q / QPERCTA, NSEG / SEGS_PER_CTA);   // 32 x 32 = 1024 CTAs
    knn_segmin_kernel<<<gridA, QBLOCK>>>(qp, rp);
    knn_finish_kernel<<<N_Q / 4, 128>>>(qp, rp, rf, out);  // warp per query
    nop_kernel<<<1, 32>>>();                   // period-3 profiler alignment
}